// round 1
// baseline (speedup 1.0000x reference)
#include <cuda_runtime.h>

// Problem constants
#define BB     64
#define SS     2048
#define INDIM  512
#define HH     512
#define NCTA   128           // scan grid: 16 batch-slices x 8 hidden-slices
#define WS_STRIDE 68         // 64 j + 4 pad (conflict-free LDS.128, keeps 16B align)

#define SCAN_SMEM_FLOATS (512 * WS_STRIDE + 4 * 512 + 1024)
#define SCAN_SMEM_BYTES  (SCAN_SMEM_FLOATS * 4)

typedef unsigned long long ull;

// ---------------- packed f32x2 helpers (FFMA2 path, sm_103a) ----------------
__device__ __forceinline__ void ffma2(ull& acc, ull a, ull b) {
    asm volatile("fma.rn.f32x2 %0, %1, %2, %0;" : "+l"(acc) : "l"(a), "l"(b));
}
__device__ __forceinline__ ull pack2(float x) {
    ull r; asm("mov.b64 %0, {%1, %1};" : "=l"(r) : "f"(x)); return r;
}
__device__ __forceinline__ float2 unpack2(ull v) {
    float2 r; asm("mov.b64 {%0, %1}, %2;" : "=f"(r.x), "=f"(r.y) : "l"(v)); return r;
}

// ---------------- Phase 1: x_proj = inputs @ W_ih^T + b_ih ----------------
// C[m, h] = sum_i A[m, i] * W[h, i] + bias[h]
// A: [131072, 512] row-major, W: [512, 512] row-major, C -> d_out (outs region)
__global__ __launch_bounds__(256) void xproj_kernel(
    const float* __restrict__ A, const float* __restrict__ W,
    const float* __restrict__ bias, float* __restrict__ C) {
    __shared__ float As[16][132];   // [k][m], padded
    __shared__ float Bs[16][132];   // [k][n], padded

    const int tid = threadIdx.x;
    const int m0 = blockIdx.x * 128;
    const int n0 = blockIdx.y * 128;
    const int lr = tid >> 2;            // 0..63
    const int lk = (tid & 3) << 2;      // 0,4,8,12
    const int tx = tid & 15;            // n micro-group
    const int ty = tid >> 4;            // m micro-group

    ull acc[8][4];
#pragma unroll
    for (int i = 0; i < 8; i++)
#pragma unroll
        for (int j = 0; j < 4; j++) acc[i][j] = 0ull;

    for (int k0 = 0; k0 < INDIM; k0 += 16) {
        float4 a0 = *(const float4*)(A + (size_t)(m0 + lr) * INDIM + k0 + lk);
        float4 a1 = *(const float4*)(A + (size_t)(m0 + lr + 64) * INDIM + k0 + lk);
        float4 w0 = *(const float4*)(W + (size_t)(n0 + lr) * INDIM + k0 + lk);
        float4 w1 = *(const float4*)(W + (size_t)(n0 + lr + 64) * INDIM + k0 + lk);
        __syncthreads();
        As[lk + 0][lr] = a0.x; As[lk + 1][lr] = a0.y; As[lk + 2][lr] = a0.z; As[lk + 3][lr] = a0.w;
        As[lk + 0][lr + 64] = a1.x; As[lk + 1][lr + 64] = a1.y; As[lk + 2][lr + 64] = a1.z; As[lk + 3][lr + 64] = a1.w;
        Bs[lk + 0][lr] = w0.x; Bs[lk + 1][lr] = w0.y; Bs[lk + 2][lr] = w0.z; Bs[lk + 3][lr] = w0.w;
        Bs[lk + 0][lr + 64] = w1.x; Bs[lk + 1][lr + 64] = w1.y; Bs[lk + 2][lr + 64] = w1.z; Bs[lk + 3][lr + 64] = w1.w;
        __syncthreads();
#pragma unroll
        for (int k = 0; k < 16; k++) {
            float4 am0 = *(const float4*)&As[k][ty * 4];
            float4 am1 = *(const float4*)&As[k][64 + ty * 4];
            ulonglong2 bn0 = *(const ulonglong2*)&Bs[k][tx * 4];
            ulonglong2 bn1 = *(const ulonglong2*)&Bs[k][64 + tx * 4];
            float am[8] = {am0.x, am0.y, am0.z, am0.w, am1.x, am1.y, am1.z, am1.w};
#pragma unroll
            for (int i = 0; i < 8; i++) {
                ull ap = pack2(am[i]);
                ffma2(acc[i][0], ap, bn0.x);
                ffma2(acc[i][1], ap, bn0.y);
                ffma2(acc[i][2], ap, bn1.x);
                ffma2(acc[i][3], ap, bn1.y);
            }
        }
    }

    float4 bA = *(const float4*)(bias + n0 + tx * 4);
    float4 bBv = *(const float4*)(bias + n0 + 64 + tx * 4);
#pragma unroll
    for (int i = 0; i < 8; i++) {
        int m = m0 + ((i < 4) ? (ty * 4 + i) : (64 + ty * 4 + (i - 4)));
        float2 c0 = unpack2(acc[i][0]);
        float2 c1 = unpack2(acc[i][1]);
        float2 c2 = unpack2(acc[i][2]);
        float2 c3 = unpack2(acc[i][3]);
        float4 o0 = make_float4(c0.x + bA.x, c0.y + bA.y, c1.x + bA.z, c1.y + bA.w);
        float4 o1 = make_float4(c2.x + bBv.x, c2.y + bBv.y, c3.x + bBv.z, c3.y + bBv.w);
        *(float4*)(C + (size_t)m * HH + n0 + tx * 4) = o0;
        *(float4*)(C + (size_t)m * HH + n0 + 64 + tx * 4) = o1;
    }
}

// ---------------- Phase 2: persistent sequential scan ----------------
__device__ float g_h[2][BB * HH];       // double-buffered hidden state
__device__ unsigned g_count = 0;        // barrier arrivals
__device__ unsigned g_sense = 0;        // barrier sense

__device__ __forceinline__ void gbar(unsigned& ls) {
    __syncthreads();
    if (threadIdx.x == 0) {
        __threadfence();
        if (atomicAdd(&g_count, 1u) == NCTA - 1) {
            atomicExch(&g_count, 0u);
            __threadfence();
            atomicExch(&g_sense, ls);
        } else {
            while (*(volatile unsigned*)&g_sense != ls) { }
        }
        __threadfence();
        ls ^= 1u;
    }
    __syncthreads();
}

__global__ __launch_bounds__(256, 1) void rnn_scan_kernel(
    const float* __restrict__ h0, const float* __restrict__ W_hh,
    const float* __restrict__ b_hh, float* __restrict__ out, int write_hfinal) {
    extern __shared__ float sm[];
    float* Ws  = sm;                         // [512 k][WS_STRIDE] (64 j used)
    float* hs  = sm + 512 * WS_STRIDE;       // [4 b][512 k]
    float* red = hs + 4 * 512;               // [4 ks][4 b][64 j]

    const int tid = threadIdx.x;
    const int cta = blockIdx.x;
    const int j0 = (cta & 7) * 64;           // hidden slice
    const int b0 = (cta >> 3) * 4;           // batch slice

    // compute mapping: 16 j-groups x 4 b x 4 k-chunks
    const int jg = tid & 15;
    const int cb = (tid >> 4) & 3;
    const int ks = tid >> 6;
    // output mapping: (b, j)
    const int ob = tid >> 6;                 // 0..3
    const int oj = tid & 63;                 // 0..63

    // Load W_hh slice into smem, k-major (resident for all 2048 steps)
    for (int idx = tid; idx < 64 * 512; idx += 256) {
        int jj = idx >> 9;
        int k  = idx & 511;
        Ws[k * WS_STRIDE + jj] = W_hh[(size_t)(j0 + jj) * 512 + k];
    }
    const float bh = b_hh[j0 + oj];

    // Init h buffer 0 from h0 (each CTA covers its (b-slice, j-slice) block)
    {
        float v = h0[(size_t)(b0 + ob) * HH + j0 + oj];
        __stcg(&g_h[0][(b0 + ob) * HH + j0 + oj], v);
    }

    // Dynamic initial barrier sense: parity-safe across graph replays
    unsigned ls = 0;
    if (tid == 0) ls = (*(volatile unsigned*)&g_sense) ^ 1u;
    gbar(ls);

    const size_t obase = (size_t)(b0 + ob) * SS * HH + (size_t)(j0 + oj);
    float hlast = 0.f;

    for (int t = 0; t < SS; ++t) {
        const float* hin = g_h[t & 1];
        float* hout = g_h[(t & 1) ^ 1];

        // Prefetch this thread's x_proj element (read-once stream)
        float xp = __ldcs(out + obase + (size_t)t * HH);

        // Stage 4 h rows (2048 floats) from L2 into smem, .cg to dodge stale L1
        const float4* src = (const float4*)(hin + b0 * HH);
        float4* dst = (float4*)hs;
        dst[tid] = __ldcg(src + tid);
        dst[tid + 256] = __ldcg(src + tid + 256);
        __syncthreads();

        // Partial dot: 4 j outputs x 1 b over a 128-wide k chunk, FFMA2
        ull a01 = 0ull, a23 = 0ull;
        const float* hrow = hs + cb * 512 + ks * 128;
        const float* wrow = Ws + (ks * 128) * WS_STRIDE + jg * 4;
#pragma unroll 4
        for (int kk = 0; kk < 128; kk += 4) {
            float4 hv = *(const float4*)(hrow + kk);
            ulonglong2 w0 = *(const ulonglong2*)(wrow + (size_t)(kk + 0) * WS_STRIDE);
            ull hp = pack2(hv.x); ffma2(a01, hp, w0.x); ffma2(a23, hp, w0.y);
            ulonglong2 w1 = *(const ulonglong2*)(wrow + (size_t)(kk + 1) * WS_STRIDE);
            hp = pack2(hv.y); ffma2(a01, hp, w1.x); ffma2(a23, hp, w1.y);
            ulonglong2 w2 = *(const ulonglong2*)(wrow + (size_t)(kk + 2) * WS_STRIDE);
            hp = pack2(hv.z); ffma2(a01, hp, w2.x); ffma2(a23, hp, w2.y);
            ulonglong2 w3 = *(const ulonglong2*)(wrow + (size_t)(kk + 3) * WS_STRIDE);
            hp = pack2(hv.w); ffma2(a01, hp, w3.x); ffma2(a23, hp, w3.y);
        }
        float2 p01 = unpack2(a01);
        float2 p23 = unpack2(a23);
        *(float4*)(red + ks * 256 + cb * 64 + jg * 4) = make_float4(p01.x, p01.y, p23.x, p23.y);
        __syncthreads();

        // Reduce 4 k-chunks, tanh, emit
        float a = red[ob * 64 + oj] + red[256 + ob * 64 + oj] +
                  red[512 + ob * 64 + oj] + red[768 + ob * 64 + oj];
        float hv = tanhf(xp + a + bh);
        out[obase + (size_t)t * HH] = hv;
        __stcg(&hout[(b0 + ob) * HH + j0 + oj], hv);
        hlast = hv;

        gbar(ls);
    }

    if (write_hfinal)
        out[(size_t)BB * SS * HH + (size_t)(b0 + ob) * HH + (j0 + oj)] = hlast;
}

// ---------------- launch ----------------
extern "C" void kernel_launch(void* const* d_in, const int* in_sizes, int n_in,
                              void* d_out, int out_size) {
    const float* inputs = (const float*)d_in[0];   // [64, 2048, 512]
    const float* h0     = (const float*)d_in[1];   // [64, 512]
    const float* W_ih   = (const float*)d_in[2];   // [512, 512]
    const float* W_hh   = (const float*)d_in[3];   // [512, 512]
    const float* b_ih   = (const float*)d_in[4];   // [512]
    const float* b_hh   = (const float*)d_in[5];   // [512]
    float* out = (float*)d_out;

    cudaFuncSetAttribute(rnn_scan_kernel,
                         cudaFuncAttributeMaxDynamicSharedMemorySize,
                         SCAN_SMEM_BYTES);

    // Phase 1: x_proj into the outs region of d_out (scan overwrites in place)
    dim3 g1((BB * SS) / 128, HH / 128, 1);
    xproj_kernel<<<g1, 256>>>(inputs, W_ih, b_ih, out);

    // Phase 2: persistent scan (128 CTAs, single wave, grid spin-barrier)
    long long need = (long long)BB * SS * HH + (long long)BB * HH;
    int wf = ((long long)out_size >= need) ? 1 : 0;
    rnn_scan_kernel<<<NCTA, 256, SCAN_SMEM_BYTES>>>(h0, W_hh, b_hh, out, wf);
}

// round 2
// speedup vs baseline: 1.1048x; 1.1048x over previous
#include <cuda_runtime.h>
#include <cstdint>

// Problem constants
#define BB     64
#define SS     2048
#define INDIM  512
#define HH     512
#define CLUSTER_NCTA 8
#define NCTA   128           // 16 clusters x 8 CTAs

typedef unsigned long long ull;

// ---------------- packed f32x2 helpers (FFMA2 path, sm_103a) ----------------
__device__ __forceinline__ void ffma2(ull& acc, ull a, ull b) {
    asm volatile("fma.rn.f32x2 %0, %1, %2, %0;" : "+l"(acc) : "l"(a), "l"(b));
}
__device__ __forceinline__ ull pack2(float x) {
    ull r; asm("mov.b64 %0, {%1, %1};" : "=l"(r) : "f"(x)); return r;
}
__device__ __forceinline__ float2 unpack2(ull v) {
    float2 r; asm("mov.b64 {%0, %1}, %2;" : "=f"(r.x), "=f"(r.y) : "l"(v)); return r;
}
__device__ __forceinline__ uint32_t smem_u32(const void* p) {
    uint32_t a;
    asm("{ .reg .u64 t; cvta.to.shared.u64 t, %1; cvt.u32.u64 %0, t; }" : "=r"(a) : "l"(p));
    return a;
}
__device__ __forceinline__ uint32_t mapa_rank(uint32_t laddr, uint32_t rank) {
    uint32_t r;
    asm("mapa.shared::cluster.u32 %0, %1, %2;" : "=r"(r) : "r"(laddr), "r"(rank));
    return r;
}
__device__ __forceinline__ void st_cluster_f32(uint32_t raddr, float v) {
    asm volatile("st.shared::cluster.f32 [%0], %1;" :: "r"(raddr), "f"(v) : "memory");
}

// ---------------- Phase 1: x_proj = inputs @ W_ih^T + b_ih ----------------
__global__ __launch_bounds__(256) void xproj_kernel(
    const float* __restrict__ A, const float* __restrict__ W,
    const float* __restrict__ bias, float* __restrict__ C) {
    __shared__ float As[16][132];
    __shared__ float Bs[16][132];

    const int tid = threadIdx.x;
    const int m0 = blockIdx.x * 128;
    const int n0 = blockIdx.y * 128;
    const int lr = tid >> 2;
    const int lk = (tid & 3) << 2;
    const int tx = tid & 15;
    const int ty = tid >> 4;

    ull acc[8][4];
#pragma unroll
    for (int i = 0; i < 8; i++)
#pragma unroll
        for (int j = 0; j < 4; j++) acc[i][j] = 0ull;

    for (int k0 = 0; k0 < INDIM; k0 += 16) {
        float4 a0 = *(const float4*)(A + (size_t)(m0 + lr) * INDIM + k0 + lk);
        float4 a1 = *(const float4*)(A + (size_t)(m0 + lr + 64) * INDIM + k0 + lk);
        float4 w0 = *(const float4*)(W + (size_t)(n0 + lr) * INDIM + k0 + lk);
        float4 w1 = *(const float4*)(W + (size_t)(n0 + lr + 64) * INDIM + k0 + lk);
        __syncthreads();
        As[lk + 0][lr] = a0.x; As[lk + 1][lr] = a0.y; As[lk + 2][lr] = a0.z; As[lk + 3][lr] = a0.w;
        As[lk + 0][lr + 64] = a1.x; As[lk + 1][lr + 64] = a1.y; As[lk + 2][lr + 64] = a1.z; As[lk + 3][lr + 64] = a1.w;
        Bs[lk + 0][lr] = w0.x; Bs[lk + 1][lr] = w0.y; Bs[lk + 2][lr] = w0.z; Bs[lk + 3][lr] = w0.w;
        Bs[lk + 0][lr + 64] = w1.x; Bs[lk + 1][lr + 64] = w1.y; Bs[lk + 2][lr + 64] = w1.z; Bs[lk + 3][lr + 64] = w1.w;
        __syncthreads();
#pragma unroll
        for (int k = 0; k < 16; k++) {
            float4 am0 = *(const float4*)&As[k][ty * 4];
            float4 am1 = *(const float4*)&As[k][64 + ty * 4];
            ulonglong2 bn0 = *(const ulonglong2*)&Bs[k][tx * 4];
            ulonglong2 bn1 = *(const ulonglong2*)&Bs[k][64 + tx * 4];
            float am[8] = {am0.x, am0.y, am0.z, am0.w, am1.x, am1.y, am1.z, am1.w};
#pragma unroll
            for (int i = 0; i < 8; i++) {
                ull ap = pack2(am[i]);
                ffma2(acc[i][0], ap, bn0.x);
                ffma2(acc[i][1], ap, bn0.y);
                ffma2(acc[i][2], ap, bn1.x);
                ffma2(acc[i][3], ap, bn1.y);
            }
        }
    }

    float4 bA = *(const float4*)(bias + n0 + tx * 4);
    float4 bBv = *(const float4*)(bias + n0 + 64 + tx * 4);
#pragma unroll
    for (int i = 0; i < 8; i++) {
        int m = m0 + ((i < 4) ? (ty * 4 + i) : (64 + ty * 4 + (i - 4)));
        float2 c0 = unpack2(acc[i][0]);
        float2 c1 = unpack2(acc[i][1]);
        float2 c2 = unpack2(acc[i][2]);
        float2 c3 = unpack2(acc[i][3]);
        float4 o0 = make_float4(c0.x + bA.x, c0.y + bA.y, c1.x + bA.z, c1.y + bA.w);
        float4 o1 = make_float4(c2.x + bBv.x, c2.y + bBv.y, c3.x + bBv.z, c3.y + bBv.w);
        *(float4*)(C + (size_t)m * HH + n0 + tx * 4) = o0;
        *(float4*)(C + (size_t)m * HH + n0 + 64 + tx * 4) = o1;
    }
}

// ---------------- Phase 2: clustered persistent scan ----------------
// Cluster of 8 CTAs = one batch-slice of 4 batches. CTA rank r owns j-slice
// [64r, 64r+64). W_hh slice lives in REGISTERS (lane l of warp w holds
// W[2l..2l+1][64w..64w+64) as 64 k-paired ull). h lives in smem, double
// buffered, exchanged intra-cluster via DSMEM stores + cluster barrier.
__global__ __launch_bounds__(256, 1) __cluster_dims__(CLUSTER_NCTA, 1, 1)
void rnn_scan_kernel(
    const float* __restrict__ h0, const float* __restrict__ W_hh,
    const float* __restrict__ b_hh, float* __restrict__ out, int write_hfinal) {
    // hsp[buf][kp][b] : ull = (h[b][2kp], h[b][2kp+1])
    __shared__ ull hsp[2][256][4];
    __shared__ float redA[8][32][4];   // warp, lane(j-pair), batch  (jj=0)
    __shared__ float redB[8][32][4];   // jj=1

    const int tid = threadIdx.x;
    const int w = tid >> 5;          // warp 0..7 -> k-chunk
    const int l = tid & 31;          // lane -> j-pair
    uint32_t rank;
    asm("mov.u32 %0, %%cluster_ctarank;" : "=r"(rank));
    const int j0 = (int)rank * 64;
    const int b0 = (blockIdx.x >> 3) * 4;

    // output mapping
    const int ob = tid >> 6;         // 0..3 batch
    const int oj = tid & 63;         // 0..63 hidden within slice

    // ---- load W slice into registers, packed over k pairs ----
    const int kc = w * 64;
    ull Wp0[32], Wp1[32];
    {
        const ull* w0p = (const ull*)(W_hh + (size_t)(j0 + 2 * l) * HH + kc);
        const ull* w1p = (const ull*)(W_hh + (size_t)(j0 + 2 * l + 1) * HH + kc);
#pragma unroll
        for (int p = 0; p < 32; p++) { Wp0[p] = w0p[p]; Wp1[p] = w1p[p]; }
    }
    const float bh = b_hh[j0 + oj];

    // ---- init h buffer 0 from h0 (own CTA's full 4x512 block) ----
    {
        float* hf = (float*)&hsp[0][0][0];
        for (int i = tid; i < 4 * HH; i += 256) {
            int b = i >> 9, k = i & 511;
            hf[((k >> 1) * 4 + b) * 2 + (k & 1)] = h0[(size_t)(b0 + b) * HH + k];
        }
    }
    __syncthreads();

    // precompute DSMEM remote base addresses for the scatter
    const uint32_t hsp_base = smem_u32(&hsp[0][0][0]);
    uint32_t rbase[CLUSTER_NCTA];
#pragma unroll
    for (int r = 0; r < CLUSTER_NCTA; r++) rbase[r] = mapa_rank(hsp_base, r);

    const int gj = j0 + oj;
    const uint32_t scat_off0 = ((uint32_t)(gj >> 1) * 4 + ob) * 8 + (gj & 1) * 4;

    const size_t obase = ((size_t)(b0 + ob) * SS) * HH + gj;
    float xp = __ldcs(out + obase);           // prefetch step 0
    float hlast = 0.f;

    for (int t = 0; t < SS; ++t) {
        const int cur = t & 1;
        const ull* hb = &hsp[cur][w * 32][0];

        // ---- 2j x 4b x 64k per thread, W in regs, h broadcast from smem ----
        ull a0b0 = 0, a0b1 = 0, a0b2 = 0, a0b3 = 0;
        ull a1b0 = 0, a1b1 = 0, a1b2 = 0, a1b3 = 0;
#pragma unroll
        for (int p = 0; p < 32; p++) {
            ulonglong2 h01 = *(const ulonglong2*)(hb + p * 4);
            ulonglong2 h23 = *(const ulonglong2*)(hb + p * 4 + 2);
            ull w0 = Wp0[p], w1 = Wp1[p];
            ffma2(a0b0, h01.x, w0); ffma2(a1b0, h01.x, w1);
            ffma2(a0b1, h01.y, w0); ffma2(a1b1, h01.y, w1);
            ffma2(a0b2, h23.x, w0); ffma2(a1b2, h23.x, w1);
            ffma2(a0b3, h23.y, w0); ffma2(a1b3, h23.y, w1);
        }
        // fold k parity and stash partials
        {
            float2 f;
            float4 ra, rb;
            f = unpack2(a0b0); ra.x = f.x + f.y;
            f = unpack2(a0b1); ra.y = f.x + f.y;
            f = unpack2(a0b2); ra.z = f.x + f.y;
            f = unpack2(a0b3); ra.w = f.x + f.y;
            f = unpack2(a1b0); rb.x = f.x + f.y;
            f = unpack2(a1b1); rb.y = f.x + f.y;
            f = unpack2(a1b2); rb.z = f.x + f.y;
            f = unpack2(a1b3); rb.w = f.x + f.y;
            *(float4*)&redA[w][l][0] = ra;
            *(float4*)&redB[w][l][0] = rb;
        }
        __syncthreads();

        // ---- reduce 8 k-chunks, tanh ----
        const float* rbase_f = (oj & 1) ? &redB[0][0][0] : &redA[0][0][0];
        const int ri = (oj >> 1) * 4 + ob;
        float a = rbase_f[ri] + rbase_f[128 + ri] + rbase_f[256 + ri] + rbase_f[384 + ri]
                + rbase_f[512 + ri] + rbase_f[640 + ri] + rbase_f[768 + ri] + rbase_f[896 + ri];
        float hv = tanhf(xp + a + bh);

        // ---- scatter h to all 8 cluster CTAs' next buffer (incl. self) ----
        const uint32_t soff = scat_off0 + (uint32_t)((t & 1) ^ 1) * (256 * 4 * 8);
#pragma unroll
        for (int r = 0; r < CLUSTER_NCTA; r++)
            st_cluster_f32(rbase[r] + soff, hv);

        asm volatile("barrier.cluster.arrive.aligned;" ::: "memory");

        // overlap with barrier: emit output, prefetch next xp
        out[obase + (size_t)t * HH] = hv;
        hlast = hv;
        if (t + 1 < SS) xp = __ldcs(out + obase + (size_t)(t + 1) * HH);

        asm volatile("barrier.cluster.wait.aligned;" ::: "memory");
    }

    if (write_hfinal)
        out[(size_t)BB * SS * HH + (size_t)(b0 + ob) * HH + gj] = hlast;
}

// ---------------- launch ----------------
extern "C" void kernel_launch(void* const* d_in, const int* in_sizes, int n_in,
                              void* d_out, int out_size) {
    const float* inputs = (const float*)d_in[0];   // [64, 2048, 512]
    const float* h0     = (const float*)d_in[1];   // [64, 512]
    const float* W_ih   = (const float*)d_in[2];   // [512, 512]
    const float* W_hh   = (const float*)d_in[3];   // [512, 512]
    const float* b_ih   = (const float*)d_in[4];   // [512]
    const float* b_hh   = (const float*)d_in[5];   // [512]
    float* out = (float*)d_out;

    // Phase 1: x_proj into the outs region of d_out (scan overwrites in place)
    dim3 g1((BB * SS) / 128, HH / 128, 1);
    xproj_kernel<<<g1, 256>>>(inputs, W_ih, b_ih, out);

    // Phase 2: 16 independent clusters of 8 CTAs, one wave, intra-cluster sync
    long long need = (long long)BB * SS * HH + (long long)BB * HH;
    int wf = ((long long)out_size >= need) ? 1 : 0;
    rnn_scan_kernel<<<NCTA, 256>>>(h0, W_hh, b_hh, out, wf);
}

// round 3
// speedup vs baseline: 1.2994x; 1.1761x over previous
#include <cuda_runtime.h>
#include <cstdint>

// Problem constants
#define BB     64
#define SS     2048
#define INDIM  512
#define HH     512
#define CL     8            // cluster size (j-split of W_hh)
#define NCTA   128          // 16 clusters x 8 CTAs

typedef unsigned long long ull;

// ---------------- packed f32x2 helpers (FFMA2 path, sm_103a) ----------------
__device__ __forceinline__ void ffma2(ull& acc, ull a, ull b) {
    asm volatile("fma.rn.f32x2 %0, %1, %2, %0;" : "+l"(acc) : "l"(a), "l"(b));
}
__device__ __forceinline__ ull pack2(float x) {
    ull r; asm("mov.b64 %0, {%1, %1};" : "=l"(r) : "f"(x)); return r;
}
__device__ __forceinline__ float2 unpack2(ull v) {
    float2 r; asm("mov.b64 {%0, %1}, %2;" : "=f"(r.x), "=f"(r.y) : "l"(v)); return r;
}
__device__ __forceinline__ uint32_t smem_u32(const void* p) {
    uint32_t a;
    asm("{ .reg .u64 t; cvta.to.shared.u64 t, %1; cvt.u32.u64 %0, t; }" : "=r"(a) : "l"(p));
    return a;
}
__device__ __forceinline__ uint32_t mapa_rank(uint32_t laddr, uint32_t rank) {
    uint32_t r;
    asm("mapa.shared::cluster.u32 %0, %1, %2;" : "=r"(r) : "r"(laddr), "r"(rank));
    return r;
}
__device__ __forceinline__ void mbar_init(uint32_t mbar, uint32_t cnt) {
    asm volatile("mbarrier.init.shared.b64 [%0], %1;" :: "r"(mbar), "r"(cnt) : "memory");
}
__device__ __forceinline__ void mbar_arrive_expect_tx(uint32_t mbar, uint32_t tx) {
    asm volatile("mbarrier.arrive.expect_tx.shared.b64 _, [%0], %1;"
                 :: "r"(mbar), "r"(tx) : "memory");
}
__device__ __forceinline__ void mbar_wait_cluster(uint32_t mbar, uint32_t parity) {
    asm volatile(
        "{\n\t.reg .pred P;\n\t"
        "WL_%=:\n\t"
        "mbarrier.try_wait.parity.acquire.cluster.shared::cta.b64 P, [%0], %1, 0x989680;\n\t"
        "@!P bra WL_%=;\n\t}"
        :: "r"(mbar), "r"(parity) : "memory");
}
// remote smem store that signals the co-located remote mbarrier with tx bytes
__device__ __forceinline__ void st_async_b64(uint32_t raddr, ull v, uint32_t rmbar) {
    asm volatile("st.async.shared::cluster.mbarrier::complete_tx::bytes.b64 [%0], %1, [%2];"
                 :: "r"(raddr), "l"(v), "r"(rmbar) : "memory");
}

// ---------------- Phase 1: x_proj = inputs @ W_ih^T + b_ih ----------------
__global__ __launch_bounds__(256) void xproj_kernel(
    const float* __restrict__ A, const float* __restrict__ W,
    const float* __restrict__ bias, float* __restrict__ C) {
    __shared__ float As[16][132];
    __shared__ float Bs[16][132];

    const int tid = threadIdx.x;
    const int m0 = blockIdx.x * 128;
    const int n0 = blockIdx.y * 128;
    const int lr = tid >> 2;
    const int lk = (tid & 3) << 2;
    const int tx = tid & 15;
    const int ty = tid >> 4;

    ull acc[8][4];
#pragma unroll
    for (int i = 0; i < 8; i++)
#pragma unroll
        for (int j = 0; j < 4; j++) acc[i][j] = 0ull;

    for (int k0 = 0; k0 < INDIM; k0 += 16) {
        float4 a0 = *(const float4*)(A + (size_t)(m0 + lr) * INDIM + k0 + lk);
        float4 a1 = *(const float4*)(A + (size_t)(m0 + lr + 64) * INDIM + k0 + lk);
        float4 w0 = *(const float4*)(W + (size_t)(n0 + lr) * INDIM + k0 + lk);
        float4 w1 = *(const float4*)(W + (size_t)(n0 + lr + 64) * INDIM + k0 + lk);
        __syncthreads();
        As[lk + 0][lr] = a0.x; As[lk + 1][lr] = a0.y; As[lk + 2][lr] = a0.z; As[lk + 3][lr] = a0.w;
        As[lk + 0][lr + 64] = a1.x; As[lk + 1][lr + 64] = a1.y; As[lk + 2][lr + 64] = a1.z; As[lk + 3][lr + 64] = a1.w;
        Bs[lk + 0][lr] = w0.x; Bs[lk + 1][lr] = w0.y; Bs[lk + 2][lr] = w0.z; Bs[lk + 3][lr] = w0.w;
        Bs[lk + 0][lr + 64] = w1.x; Bs[lk + 1][lr + 64] = w1.y; Bs[lk + 2][lr + 64] = w1.z; Bs[lk + 3][lr + 64] = w1.w;
        __syncthreads();
#pragma unroll
        for (int k = 0; k < 16; k++) {
            float4 am0 = *(const float4*)&As[k][ty * 4];
            float4 am1 = *(const float4*)&As[k][64 + ty * 4];
            ulonglong2 bn0 = *(const ulonglong2*)&Bs[k][tx * 4];
            ulonglong2 bn1 = *(const ulonglong2*)&Bs[k][64 + tx * 4];
            float am[8] = {am0.x, am0.y, am0.z, am0.w, am1.x, am1.y, am1.z, am1.w};
#pragma unroll
            for (int i = 0; i < 8; i++) {
                ull ap = pack2(am[i]);
                ffma2(acc[i][0], ap, bn0.x);
                ffma2(acc[i][1], ap, bn0.y);
                ffma2(acc[i][2], ap, bn1.x);
                ffma2(acc[i][3], ap, bn1.y);
            }
        }
    }

    float4 bA = *(const float4*)(bias + n0 + tx * 4);
    float4 bBv = *(const float4*)(bias + n0 + 64 + tx * 4);
#pragma unroll
    for (int i = 0; i < 8; i++) {
        int m = m0 + ((i < 4) ? (ty * 4 + i) : (64 + ty * 4 + (i - 4)));
        float2 c0 = unpack2(acc[i][0]);
        float2 c1 = unpack2(acc[i][1]);
        float2 c2 = unpack2(acc[i][2]);
        float2 c3 = unpack2(acc[i][3]);
        float4 o0 = make_float4(c0.x + bA.x, c0.y + bA.y, c1.x + bA.z, c1.y + bA.w);
        float4 o1 = make_float4(c2.x + bBv.x, c2.y + bBv.y, c3.x + bBv.z, c3.y + bBv.w);
        *(float4*)(C + (size_t)m * HH + n0 + tx * 4) = o0;
        *(float4*)(C + (size_t)m * HH + n0 + 64 + tx * 4) = o1;
    }
}

// ---------------- Phase 2: clustered scan, mbarrier + st.async exchange ----
// Cluster of 8 CTAs = 4 batches. Rank r owns j in [64r, 64r+64); its W slice
// lives in registers. h double-buffered in smem; exchanged with st.async
// (complete_tx) into per-CTA mbarriers — no full-cluster rendezvous.
__global__ __launch_bounds__(256, 1) __cluster_dims__(CL, 1, 1)
void rnn_scan_kernel(
    const float* __restrict__ h0, const float* __restrict__ W_hh,
    const float* __restrict__ b_hh, float* __restrict__ out, int write_hfinal) {
    __shared__ ull   hsp[2][256][4];        // [slot][k-pair][batch] = 16KB
    __shared__ float red[2][2][8][32][4];   // [slot][jpar][warp][jp][b] = 16KB
    __shared__ ull   mbars[2];

    const int tid = threadIdx.x;
    const int w = tid >> 5;            // warp -> k-chunk [64w, 64w+64)
    const int l = tid & 31;            // lane -> j-pair {2l, 2l+1}
    uint32_t rank;
    asm("mov.u32 %0, %%cluster_ctarank;" : "=r"(rank));
    const int j0 = (int)rank * 64;
    const int b0 = (blockIdx.x >> 3) * 4;
    const int ob = tid >> 6;           // output batch 0..3
    const int oj = tid & 63;           // output j within slice
    const int gj = j0 + oj;

    // ---- W slice into registers, k-paired ----
    ull Wp0[32], Wp1[32];
    {
        const ull* w0p = (const ull*)(W_hh + (size_t)(j0 + 2 * l) * HH + w * 64);
        const ull* w1p = (const ull*)(W_hh + (size_t)(j0 + 2 * l + 1) * HH + w * 64);
#pragma unroll
        for (int p = 0; p < 32; p++) { Wp0[p] = w0p[p]; Wp1[p] = w1p[p]; }
    }
    const float bh = b_hh[gj];

    // ---- init h slot 0 from h0 ----
    {
        float* hf = (float*)&hsp[0][0][0];
        for (int i = tid; i < 4 * HH; i += 256) {
            int b = i >> 9, k = i & 511;
            hf[(k >> 1) * 8 + b * 2 + (k & 1)] = h0[(size_t)(b0 + b) * HH + k];
        }
    }

    const uint32_t mb_local = smem_u32(&mbars[0]);
    if (tid == 0) {
        mbar_init(mb_local, 1);
        mbar_init(mb_local + 8, 1);
        mbar_arrive_expect_tx(mb_local, 8192u);       // slot0: t=1 scatters
        mbar_arrive_expect_tx(mb_local + 8, 8192u);   // slot1: t=0 scatters
        asm volatile("fence.mbarrier_init.release.cluster;" ::: "memory");
    }
    __syncthreads();
    asm volatile("barrier.cluster.arrive.aligned;" ::: "memory");
    asm volatile("barrier.cluster.wait.aligned;" ::: "memory");

    // remote addresses
    const uint32_t hbase = smem_u32(&hsp[0][0][0]);
    uint32_t rh[CL], rm[CL];
#pragma unroll
    for (int r = 0; r < CL; r++) {
        rh[r] = mapa_rank(hbase, (uint32_t)r);
        rm[r] = mapa_rank(mb_local, (uint32_t)r);
    }
    const uint32_t scat_off = ((uint32_t)(gj >> 1) * 4 + (uint32_t)ob) * 8u;

    const size_t obase = (size_t)(b0 + ob) * SS * HH + gj;
    float xp = __ldcs(out + obase);   // prefetch step 0 x_proj
    float hlast = 0.f;
    uint32_t ph0 = 0, ph1 = 0;

#define STEP(T, S, PH)                                                          \
  {                                                                             \
    if ((T) > 0) {                                                              \
      mbar_wait_cluster(mb_local + (S) * 8, PH);                                \
      PH ^= 1u;                                                                 \
      if (tid == 0) mbar_arrive_expect_tx(mb_local + (S) * 8, 8192u);           \
    }                                                                           \
    const ull* hb = &hsp[S][w * 32][0];                                         \
    ull a00 = 0, a01v = 0, a02 = 0, a03 = 0, a10 = 0, a11 = 0, a12 = 0, a13 = 0;\
    _Pragma("unroll")                                                           \
    for (int p = 0; p < 32; p++) {                                              \
      ulonglong2 hx = *(const ulonglong2*)(hb + p * 4);                         \
      ulonglong2 hy = *(const ulonglong2*)(hb + p * 4 + 2);                     \
      ull w0 = Wp0[p], w1 = Wp1[p];                                             \
      ffma2(a00, hx.x, w0);  ffma2(a10, hx.x, w1);                              \
      ffma2(a01v, hx.y, w0); ffma2(a11, hx.y, w1);                              \
      ffma2(a02, hy.x, w0);  ffma2(a12, hy.x, w1);                              \
      ffma2(a03, hy.y, w0);  ffma2(a13, hy.y, w1);                              \
    }                                                                           \
    { float2 f; float4 ra, rb;                                                  \
      f = unpack2(a00);  ra.x = f.x + f.y; f = unpack2(a01v); ra.y = f.x + f.y; \
      f = unpack2(a02);  ra.z = f.x + f.y; f = unpack2(a03);  ra.w = f.x + f.y; \
      f = unpack2(a10);  rb.x = f.x + f.y; f = unpack2(a11);  rb.y = f.x + f.y; \
      f = unpack2(a12);  rb.z = f.x + f.y; f = unpack2(a13);  rb.w = f.x + f.y; \
      *(float4*)&red[S][0][w][l][0] = ra;                                       \
      *(float4*)&red[S][1][w][l][0] = rb; }                                     \
    __syncthreads();                                                            \
    const float* rf = &red[S][oj & 1][0][oj >> 1][ob];                          \
    float sum = rf[0] + rf[128] + rf[256] + rf[384]                             \
              + rf[512] + rf[640] + rf[768] + rf[896];                          \
    float pre = xp + sum + bh;                                                  \
    float e = __expf(pre + pre);                                                \
    float hv = 1.f - __fdividef(2.f, e + 1.f);                                  \
    float hv2 = __shfl_down_sync(0xffffffffu, hv, 1);                           \
    if (((T) + 1 < SS) && !(oj & 1)) {                                          \
      ull v; asm("mov.b64 %0, {%1, %2};" : "=l"(v) : "f"(hv), "f"(hv2));        \
      uint32_t so = scat_off + (uint32_t)(((S) ^ 1) * 8192);                    \
      uint32_t mo = (uint32_t)(((S) ^ 1) * 8);                                  \
      _Pragma("unroll")                                                         \
      for (int r = 0; r < CL; r++) st_async_b64(rh[r] + so, v, rm[r] + mo);     \
    }                                                                           \
    __stcs(out + obase + (size_t)(T) * HH, hv);                                 \
    hlast = hv;                                                                 \
    if ((T) + 1 < SS) xp = __ldcs(out + obase + (size_t)((T) + 1) * HH);        \
  }

    for (int t = 0; t < SS; t += 2) {
        STEP(t, 0, ph0);
        STEP(t + 1, 1, ph1);
    }
#undef STEP

    if (write_hfinal)
        out[(size_t)BB * SS * HH + (size_t)(b0 + ob) * HH + gj] = hlast;
}

// ---------------- launch ----------------
extern "C" void kernel_launch(void* const* d_in, const int* in_sizes, int n_in,
                              void* d_out, int out_size) {
    const float* inputs = (const float*)d_in[0];   // [64, 2048, 512]
    const float* h0     = (const float*)d_in[1];   // [64, 512]
    const float* W_ih   = (const float*)d_in[2];   // [512, 512]
    const float* W_hh   = (const float*)d_in[3];   // [512, 512]
    const float* b_ih   = (const float*)d_in[4];   // [512]
    const float* b_hh   = (const float*)d_in[5];   // [512]
    float* out = (float*)d_out;

    // Phase 1: x_proj into the outs region of d_out (scan overwrites in place)
    dim3 g1((BB * SS) / 128, HH / 128, 1);
    xproj_kernel<<<g1, 256>>>(inputs, W_ih, b_ih, out);

    // Phase 2: 16 independent clusters of 8 CTAs, mbarrier-paced scan
    long long need = (long long)BB * SS * HH + (long long)BB * HH;
    int wf = ((long long)out_size >= need) ? 1 : 0;
    rnn_scan_kernel<<<NCTA, 256>>>(h0, W_hh, b_hh, out, wf);
}

// round 4
// speedup vs baseline: 1.5442x; 1.1885x over previous
#include <cuda_runtime.h>
#include <cstdint>

// Problem constants
#define BB     64
#define SS     2048
#define INDIM  512
#define HH     512
#define CL     8            // cluster size (j-split of W_hh)
#define NCTA   128          // 16 clusters x 8 CTAs

typedef unsigned long long ull;

// ---------------- packed f32x2 helpers (FFMA2 path, sm_103a) ----------------
__device__ __forceinline__ void ffma2(ull& acc, ull a, ull b) {
    asm volatile("fma.rn.f32x2 %0, %1, %2, %0;" : "+l"(acc) : "l"(a), "l"(b));
}
__device__ __forceinline__ ull pack2(float x) {
    ull r; asm("mov.b64 %0, {%1, %1};" : "=l"(r) : "f"(x)); return r;
}
__device__ __forceinline__ float2 unpack2(ull v) {
    float2 r; asm("mov.b64 {%0, %1}, %2;" : "=f"(r.x), "=f"(r.y) : "l"(v)); return r;
}
__device__ __forceinline__ uint32_t smem_u32(const void* p) {
    uint32_t a;
    asm("{ .reg .u64 t; cvta.to.shared.u64 t, %1; cvt.u32.u64 %0, t; }" : "=r"(a) : "l"(p));
    return a;
}
__device__ __forceinline__ uint32_t mapa_rank(uint32_t laddr, uint32_t rank) {
    uint32_t r;
    asm("mapa.shared::cluster.u32 %0, %1, %2;" : "=r"(r) : "r"(laddr), "r"(rank));
    return r;
}
__device__ __forceinline__ void mbar_init(uint32_t mbar, uint32_t cnt) {
    asm volatile("mbarrier.init.shared.b64 [%0], %1;" :: "r"(mbar), "r"(cnt) : "memory");
}
__device__ __forceinline__ void mbar_arrive_expect_tx(uint32_t mbar, uint32_t tx) {
    asm volatile("mbarrier.arrive.expect_tx.shared.b64 _, [%0], %1;"
                 :: "r"(mbar), "r"(tx) : "memory");
}
__device__ __forceinline__ void mbar_wait_cluster(uint32_t mbar, uint32_t parity) {
    asm volatile(
        "{\n\t.reg .pred P;\n\t"
        "WL_%=:\n\t"
        "mbarrier.try_wait.parity.acquire.cluster.shared::cta.b64 P, [%0], %1, 0x989680;\n\t"
        "@!P bra WL_%=;\n\t}"
        :: "r"(mbar), "r"(parity) : "memory");
}
// 1KB bulk smem->remote smem copy, complete_tx on the remote rank's mbarrier
__device__ __forceinline__ void bulk_copy_cluster(uint32_t rdst, uint32_t lsrc,
                                                  uint32_t bytes, uint32_t rmbar) {
    asm volatile(
        "cp.async.bulk.shared::cluster.shared::cta.mbarrier::complete_tx::bytes "
        "[%0], [%1], %2, [%3];"
        :: "r"(rdst), "r"(lsrc), "r"(bytes), "r"(rmbar) : "memory");
}

// ---------------- Phase 1: x_proj = inputs @ W_ih^T + b_ih ----------------
__global__ __launch_bounds__(256) void xproj_kernel(
    const float* __restrict__ A, const float* __restrict__ W,
    const float* __restrict__ bias, float* __restrict__ C) {
    __shared__ float As[16][132];
    __shared__ float Bs[16][132];

    const int tid = threadIdx.x;
    const int m0 = blockIdx.x * 128;
    const int n0 = blockIdx.y * 128;
    const int lr = tid >> 2;
    const int lk = (tid & 3) << 2;
    const int tx = tid & 15;
    const int ty = tid >> 4;

    ull acc[8][4];
#pragma unroll
    for (int i = 0; i < 8; i++)
#pragma unroll
        for (int j = 0; j < 4; j++) acc[i][j] = 0ull;

    for (int k0 = 0; k0 < INDIM; k0 += 16) {
        float4 a0 = *(const float4*)(A + (size_t)(m0 + lr) * INDIM + k0 + lk);
        float4 a1 = *(const float4*)(A + (size_t)(m0 + lr + 64) * INDIM + k0 + lk);
        float4 w0 = *(const float4*)(W + (size_t)(n0 + lr) * INDIM + k0 + lk);
        float4 w1 = *(const float4*)(W + (size_t)(n0 + lr + 64) * INDIM + k0 + lk);
        __syncthreads();
        As[lk + 0][lr] = a0.x; As[lk + 1][lr] = a0.y; As[lk + 2][lr] = a0.z; As[lk + 3][lr] = a0.w;
        As[lk + 0][lr + 64] = a1.x; As[lk + 1][lr + 64] = a1.y; As[lk + 2][lr + 64] = a1.z; As[lk + 3][lr + 64] = a1.w;
        Bs[lk + 0][lr] = w0.x; Bs[lk + 1][lr] = w0.y; Bs[lk + 2][lr] = w0.z; Bs[lk + 3][lr] = w0.w;
        Bs[lk + 0][lr + 64] = w1.x; Bs[lk + 1][lr + 64] = w1.y; Bs[lk + 2][lr + 64] = w1.z; Bs[lk + 3][lr + 64] = w1.w;
        __syncthreads();
#pragma unroll
        for (int k = 0; k < 16; k++) {
            float4 am0 = *(const float4*)&As[k][ty * 4];
            float4 am1 = *(const float4*)&As[k][64 + ty * 4];
            ulonglong2 bn0 = *(const ulonglong2*)&Bs[k][tx * 4];
            ulonglong2 bn1 = *(const ulonglong2*)&Bs[k][64 + tx * 4];
            float am[8] = {am0.x, am0.y, am0.z, am0.w, am1.x, am1.y, am1.z, am1.w};
#pragma unroll
            for (int i = 0; i < 8; i++) {
                ull ap = pack2(am[i]);
                ffma2(acc[i][0], ap, bn0.x);
                ffma2(acc[i][1], ap, bn0.y);
                ffma2(acc[i][2], ap, bn1.x);
                ffma2(acc[i][3], ap, bn1.y);
            }
        }
    }

    float4 bA = *(const float4*)(bias + n0 + tx * 4);
    float4 bBv = *(const float4*)(bias + n0 + 64 + tx * 4);
#pragma unroll
    for (int i = 0; i < 8; i++) {
        int m = m0 + ((i < 4) ? (ty * 4 + i) : (64 + ty * 4 + (i - 4)));
        float2 c0 = unpack2(acc[i][0]);
        float2 c1 = unpack2(acc[i][1]);
        float2 c2 = unpack2(acc[i][2]);
        float2 c3 = unpack2(acc[i][3]);
        float4 o0 = make_float4(c0.x + bA.x, c0.y + bA.y, c1.x + bA.z, c1.y + bA.w);
        float4 o1 = make_float4(c2.x + bBv.x, c2.y + bBv.y, c3.x + bBv.z, c3.y + bBv.w);
        *(float4*)(C + (size_t)m * HH + n0 + tx * 4) = o0;
        *(float4*)(C + (size_t)m * HH + n0 + 64 + tx * 4) = o1;
    }
}

// ---------------- Phase 2: clustered scan, bulk DSMEM exchange ----------
// Cluster of 8 CTAs = 4 batches. Rank r owns j in [64r, 64r+64); W slice in
// registers. Each step: compute, stage own 1KB h-slice locally, then 8x 1KB
// cp.async.bulk to all ranks' next h slot (one complete_tx per copy).
__global__ __launch_bounds__(256, 1) __cluster_dims__(CL, 1, 1)
void rnn_scan_kernel(
    const float* __restrict__ h0, const float* __restrict__ W_hh,
    const float* __restrict__ b_hh, float* __restrict__ out, int write_hfinal) {
    __shared__ __align__(16) ull   hsp[2][256][4];        // [slot][k-pair][batch] 16KB
    __shared__ float red[2][2][8][32][4];                 // [slot][jpar][warp][jp][b] 16KB
    __shared__ __align__(16) float stg[2][256];           // staged own slice, dest layout
    __shared__ ull   mbars[2];

    const int tid = threadIdx.x;
    const int w = tid >> 5;            // warp -> k-chunk [64w, 64w+64)
    const int l = tid & 31;            // lane -> j-pair {2l, 2l+1}
    uint32_t rank;
    asm("mov.u32 %0, %%cluster_ctarank;" : "=r"(rank));
    const int j0 = (int)rank * 64;
    const int b0 = (blockIdx.x >> 3) * 4;
    const int ob = tid >> 6;           // output batch 0..3
    const int oj = tid & 63;           // output j within slice
    const int gj = j0 + oj;

    // ---- W slice into registers, k-paired ----
    ull Wp0[32], Wp1[32];
    {
        const ull* w0p = (const ull*)(W_hh + (size_t)(j0 + 2 * l) * HH + w * 64);
        const ull* w1p = (const ull*)(W_hh + (size_t)(j0 + 2 * l + 1) * HH + w * 64);
#pragma unroll
        for (int p = 0; p < 32; p++) { Wp0[p] = w0p[p]; Wp1[p] = w1p[p]; }
    }
    const float bh = b_hh[gj];

    // ---- init h slot 0 from h0 ----
    {
        float* hf = (float*)&hsp[0][0][0];
        for (int i = tid; i < 4 * HH; i += 256) {
            int b = i >> 9, k = i & 511;
            hf[(k >> 1) * 8 + b * 2 + (k & 1)] = h0[(size_t)(b0 + b) * HH + k];
        }
    }

    const uint32_t mb_local = smem_u32(&mbars[0]);
    if (tid == 0) {
        mbar_init(mb_local, 1);
        mbar_init(mb_local + 8, 1);
        mbar_arrive_expect_tx(mb_local, 8192u);       // slot0 receives at t=1's producers
        mbar_arrive_expect_tx(mb_local + 8, 8192u);   // slot1 receives at t=0's producers
        asm volatile("fence.mbarrier_init.release.cluster;" ::: "memory");
    }
    __syncthreads();
    asm volatile("barrier.cluster.arrive.aligned;" ::: "memory");
    asm volatile("barrier.cluster.wait.aligned;" ::: "memory");

    // remote addresses
    const uint32_t hbase = smem_u32(&hsp[0][0][0]);
    const uint32_t sbase = smem_u32(&stg[0][0]);
    uint32_t rh[CL], rm[CL];
#pragma unroll
    for (int r = 0; r < CL; r++) {
        rh[r] = mapa_rank(hbase, (uint32_t)r);
        rm[r] = mapa_rank(mb_local, (uint32_t)r);
    }
    // my slice lands at byte offset rank*1024 inside each slot
    const uint32_t my_off = rank * 1024u;
    // staging index: matches destination layout within the 1KB block
    const int sidx = (oj >> 1) * 8 + ob * 2 + (oj & 1);

    const size_t obase = (size_t)(b0 + ob) * SS * HH + gj;
    float xp = __ldcs(out + obase);   // prefetch step 0 x_proj
    float hlast = 0.f;
    uint32_t ph0 = 0, ph1 = 0;

#define STEP(T, S, PH)                                                          \
  {                                                                             \
    if ((T) > 0) {                                                              \
      mbar_wait_cluster(mb_local + (S) * 8, PH);                                \
      PH ^= 1u;                                                                 \
      if (tid == 0) mbar_arrive_expect_tx(mb_local + (S) * 8, 8192u);           \
    }                                                                           \
    const ull* hb = &hsp[S][w * 32][0];                                         \
    ull a00 = 0, a01v = 0, a02 = 0, a03 = 0, a10 = 0, a11 = 0, a12 = 0, a13 = 0;\
    _Pragma("unroll")                                                           \
    for (int p = 0; p < 32; p++) {                                              \
      ulonglong2 hx = *(const ulonglong2*)(hb + p * 4);                         \
      ulonglong2 hy = *(const ulonglong2*)(hb + p * 4 + 2);                     \
      ull w0 = Wp0[p], w1 = Wp1[p];                                             \
      ffma2(a00, hx.x, w0);  ffma2(a10, hx.x, w1);                              \
      ffma2(a01v, hx.y, w0); ffma2(a11, hx.y, w1);                              \
      ffma2(a02, hy.x, w0);  ffma2(a12, hy.x, w1);                              \
      ffma2(a03, hy.y, w0);  ffma2(a13, hy.y, w1);                              \
    }                                                                           \
    { float2 f; float4 ra, rb;                                                  \
      f = unpack2(a00);  ra.x = f.x + f.y; f = unpack2(a01v); ra.y = f.x + f.y; \
      f = unpack2(a02);  ra.z = f.x + f.y; f = unpack2(a03);  ra.w = f.x + f.y; \
      f = unpack2(a10);  rb.x = f.x + f.y; f = unpack2(a11);  rb.y = f.x + f.y; \
      f = unpack2(a12);  rb.z = f.x + f.y; f = unpack2(a13);  rb.w = f.x + f.y; \
      *(float4*)&red[S][0][w][l][0] = ra;                                       \
      *(float4*)&red[S][1][w][l][0] = rb; }                                     \
    __syncthreads();                                                            \
    const float* rf = &red[S][oj & 1][0][oj >> 1][ob];                          \
    float sum = rf[0] + rf[128] + rf[256] + rf[384]                             \
              + rf[512] + rf[640] + rf[768] + rf[896];                          \
    float pre = xp + sum + bh;                                                  \
    float e = __expf(pre + pre);                                                \
    float hv = 1.f - __fdividef(2.f, e + 1.f);                                  \
    stg[S][sidx] = hv;                                                          \
    __stcs(out + obase + (size_t)(T) * HH, hv);                                 \
    hlast = hv;                                                                 \
    if ((T) + 1 < SS) xp = __ldcs(out + obase + (size_t)((T) + 1) * HH);        \
    __syncthreads();                                                            \
    if (((T) + 1 < SS) && tid < CL) {                                           \
      asm volatile("fence.proxy.async.shared::cta;" ::: "memory");              \
      bulk_copy_cluster(rh[tid] + (uint32_t)(((S) ^ 1) * 8192) + my_off,        \
                        sbase + (uint32_t)((S) * 1024), 1024u,                  \
                        rm[tid] + (uint32_t)(((S) ^ 1) * 8));                   \
    }                                                                           \
  }

    for (int t = 0; t < SS; t += 2) {
        STEP(t, 0, ph0);
        STEP(t + 1, 1, ph1);
    }
#undef STEP

    if (write_hfinal)
        out[(size_t)BB * SS * HH + (size_t)(b0 + ob) * HH + gj] = hlast;
}

// ---------------- launch ----------------
extern "C" void kernel_launch(void* const* d_in, const int* in_sizes, int n_in,
                              void* d_out, int out_size) {
    const float* inputs = (const float*)d_in[0];   // [64, 2048, 512]
    const float* h0     = (const float*)d_in[1];   // [64, 512]
    const float* W_ih   = (const float*)d_in[2];   // [512, 512]
    const float* W_hh   = (const float*)d_in[3];   // [512, 512]
    const float* b_ih   = (const float*)d_in[4];   // [512]
    const float* b_hh   = (const float*)d_in[5];   // [512]
    float* out = (float*)d_out;

    // Phase 1: x_proj into the outs region of d_out (scan overwrites in place)
    dim3 g1((BB * SS) / 128, HH / 128, 1);
    xproj_kernel<<<g1, 256>>>(inputs, W_ih, b_ih, out);

    // Phase 2: 16 independent clusters of 8 CTAs, bulk-DSMEM-paced scan
    long long need = (long long)BB * SS * HH + (long long)BB * HH;
    int wf = ((long long)out_size >= need) ? 1 : 0;
    rnn_scan_kernel<<<NCTA, 256>>>(h0, W_hh, b_hh, out, wf);
}

// round 5
// speedup vs baseline: 1.6021x; 1.0375x over previous
#include <cuda_runtime.h>
#include <cstdint>

// Problem constants
#define BB     64
#define SS     2048
#define INDIM  512
#define HH     512
#define CL     8            // cluster size (j-split of W_hh)
#define NCTA   128          // 16 clusters x 8 CTAs

typedef unsigned long long ull;

// ---------------- packed f32x2 helpers (FFMA2 path, sm_103a) ----------------
__device__ __forceinline__ void ffma2(ull& acc, ull a, ull b) {
    asm volatile("fma.rn.f32x2 %0, %1, %2, %0;" : "+l"(acc) : "l"(a), "l"(b));
}
__device__ __forceinline__ ull pack2(float x) {
    ull r; asm("mov.b64 %0, {%1, %1};" : "=l"(r) : "f"(x)); return r;
}
__device__ __forceinline__ float2 unpack2(ull v) {
    float2 r; asm("mov.b64 {%0, %1}, %2;" : "=f"(r.x), "=f"(r.y) : "l"(v)); return r;
}
__device__ __forceinline__ uint32_t smem_u32(const void* p) {
    uint32_t a;
    asm("{ .reg .u64 t; cvta.to.shared.u64 t, %1; cvt.u32.u64 %0, t; }" : "=r"(a) : "l"(p));
    return a;
}
__device__ __forceinline__ uint32_t mapa_rank(uint32_t laddr, uint32_t rank) {
    uint32_t r;
    asm("mapa.shared::cluster.u32 %0, %1, %2;" : "=r"(r) : "r"(laddr), "r"(rank));
    return r;
}
__device__ __forceinline__ void mbar_init(uint32_t mbar, uint32_t cnt) {
    asm volatile("mbarrier.init.shared.b64 [%0], %1;" :: "r"(mbar), "r"(cnt) : "memory");
}
__device__ __forceinline__ void mbar_arrive_expect_tx(uint32_t mbar, uint32_t tx) {
    asm volatile("mbarrier.arrive.expect_tx.shared.b64 _, [%0], %1;"
                 :: "r"(mbar), "r"(tx) : "memory");
}
__device__ __forceinline__ void mbar_wait_cluster(uint32_t mbar, uint32_t parity) {
    asm volatile(
        "{\n\t.reg .pred P;\n\t"
        "WL_%=:\n\t"
        "mbarrier.try_wait.parity.acquire.cluster.shared::cta.b64 P, [%0], %1, 0x989680;\n\t"
        "@!P bra WL_%=;\n\t}"
        :: "r"(mbar), "r"(parity) : "memory");
}
// bulk smem->remote smem copy, complete_tx on the remote rank's mbarrier
__device__ __forceinline__ void bulk_copy_cluster(uint32_t rdst, uint32_t lsrc,
                                                  uint32_t bytes, uint32_t rmbar) {
    asm volatile(
        "cp.async.bulk.shared::cluster.shared::cta.mbarrier::complete_tx::bytes "
        "[%0], [%1], %2, [%3];"
        :: "r"(rdst), "r"(lsrc), "r"(bytes), "r"(rmbar) : "memory");
}

// ---------------- Phase 1: x_proj = inputs @ W_ih^T + b_ih ----------------
__global__ __launch_bounds__(256) void xproj_kernel(
    const float* __restrict__ A, const float* __restrict__ W,
    const float* __restrict__ bias, float* __restrict__ C) {
    __shared__ float As[16][132];
    __shared__ float Bs[16][132];

    const int tid = threadIdx.x;
    const int m0 = blockIdx.x * 128;
    const int n0 = blockIdx.y * 128;
    const int lr = tid >> 2;
    const int lk = (tid & 3) << 2;
    const int tx = tid & 15;
    const int ty = tid >> 4;

    ull acc[8][4];
#pragma unroll
    for (int i = 0; i < 8; i++)
#pragma unroll
        for (int j = 0; j < 4; j++) acc[i][j] = 0ull;

    for (int k0 = 0; k0 < INDIM; k0 += 16) {
        float4 a0 = *(const float4*)(A + (size_t)(m0 + lr) * INDIM + k0 + lk);
        float4 a1 = *(const float4*)(A + (size_t)(m0 + lr + 64) * INDIM + k0 + lk);
        float4 w0 = *(const float4*)(W + (size_t)(n0 + lr) * INDIM + k0 + lk);
        float4 w1 = *(const float4*)(W + (size_t)(n0 + lr + 64) * INDIM + k0 + lk);
        __syncthreads();
        As[lk + 0][lr] = a0.x; As[lk + 1][lr] = a0.y; As[lk + 2][lr] = a0.z; As[lk + 3][lr] = a0.w;
        As[lk + 0][lr + 64] = a1.x; As[lk + 1][lr + 64] = a1.y; As[lk + 2][lr + 64] = a1.z; As[lk + 3][lr + 64] = a1.w;
        Bs[lk + 0][lr] = w0.x; Bs[lk + 1][lr] = w0.y; Bs[lk + 2][lr] = w0.z; Bs[lk + 3][lr] = w0.w;
        Bs[lk + 0][lr + 64] = w1.x; Bs[lk + 1][lr + 64] = w1.y; Bs[lk + 2][lr + 64] = w1.z; Bs[lk + 3][lr + 64] = w1.w;
        __syncthreads();
#pragma unroll
        for (int k = 0; k < 16; k++) {
            float4 am0 = *(const float4*)&As[k][ty * 4];
            float4 am1 = *(const float4*)&As[k][64 + ty * 4];
            ulonglong2 bn0 = *(const ulonglong2*)&Bs[k][tx * 4];
            ulonglong2 bn1 = *(const ulonglong2*)&Bs[k][64 + tx * 4];
            float am[8] = {am0.x, am0.y, am0.z, am0.w, am1.x, am1.y, am1.z, am1.w};
#pragma unroll
            for (int i = 0; i < 8; i++) {
                ull ap = pack2(am[i]);
                ffma2(acc[i][0], ap, bn0.x);
                ffma2(acc[i][1], ap, bn0.y);
                ffma2(acc[i][2], ap, bn1.x);
                ffma2(acc[i][3], ap, bn1.y);
            }
        }
    }

    float4 bA = *(const float4*)(bias + n0 + tx * 4);
    float4 bBv = *(const float4*)(bias + n0 + 64 + tx * 4);
#pragma unroll
    for (int i = 0; i < 8; i++) {
        int m = m0 + ((i < 4) ? (ty * 4 + i) : (64 + ty * 4 + (i - 4)));
        float2 c0 = unpack2(acc[i][0]);
        float2 c1 = unpack2(acc[i][1]);
        float2 c2 = unpack2(acc[i][2]);
        float2 c3 = unpack2(acc[i][3]);
        float4 o0 = make_float4(c0.x + bA.x, c0.y + bA.y, c1.x + bA.z, c1.y + bA.w);
        float4 o1 = make_float4(c2.x + bBv.x, c2.y + bBv.y, c3.x + bBv.z, c3.y + bBv.w);
        *(float4*)(C + (size_t)m * HH + n0 + tx * 4) = o0;
        *(float4*)(C + (size_t)m * HH + n0 + 64 + tx * 4) = o1;
    }
}

// ---------------- Phase 2: clustered scan, 2 interleaved batch-groups ----
// Cluster of 8 CTAs = 4 batches, split into group 0 (batches 0-1) and group 1
// (batches 2-3). Groups alternate: while group g's DSMEM exchange is in
// flight, the CTA computes the other group's step — hiding the round-trip.
__global__ __launch_bounds__(256, 1) __cluster_dims__(CL, 1, 1)
void rnn_scan_kernel(
    const float* __restrict__ h0, const float* __restrict__ W_hh,
    const float* __restrict__ b_hh, float* __restrict__ out, int write_hfinal) {
    __shared__ __align__(16) ull   hsp[2][2][256][2];   // [grp][slot][kpair][b] 16KB
    __shared__ float red[2][2][8][32][2];               // [grp][jpar][w][jp][b] 8KB
    __shared__ __align__(16) float stg[2][2][128];      // [grp][slot][slice] 2KB
    __shared__ ull   mbars[4];                          // [grp*2 + slot]

    const int tid = threadIdx.x;
    const int w = tid >> 5;            // warp -> k-chunk [64w, 64w+64)
    const int l = tid & 31;            // lane -> j-pair {2l, 2l+1}
    uint32_t rank;
    asm("mov.u32 %0, %%cluster_ctarank;" : "=r"(rank));
    const int j0 = (int)rank * 64;
    const int b0 = (blockIdx.x >> 3) * 4;
    const int obl = (tid >> 6) & 1;    // local batch within group (duplicated x2)
    const int oj = tid & 63;           // output j within slice
    const int gj = j0 + oj;

    // ---- W slice into registers, k-paired ----
    ull Wp0[32], Wp1[32];
    {
        const ull* w0p = (const ull*)(W_hh + (size_t)(j0 + 2 * l) * HH + w * 64);
        const ull* w1p = (const ull*)(W_hh + (size_t)(j0 + 2 * l + 1) * HH + w * 64);
#pragma unroll
        for (int p = 0; p < 32; p++) { Wp0[p] = w0p[p]; Wp1[p] = w1p[p]; }
    }
    const float bh = b_hh[gj];

    // ---- init h slot 0 of both groups from h0 ----
#pragma unroll
    for (int g = 0; g < 2; g++) {
        float* hf = (float*)&hsp[g][0][0][0];
        for (int i = tid; i < 2 * HH; i += 256) {
            int b = i >> 9, k = i & 511;
            hf[(k >> 1) * 4 + b * 2 + (k & 1)] = h0[(size_t)(b0 + 2 * g + b) * HH + k];
        }
    }

    const uint32_t mb_local = smem_u32(&mbars[0]);
    if (tid == 0) {
#pragma unroll
        for (int i = 0; i < 4; i++) {
            mbar_init(mb_local + 8 * i, 1);
            mbar_arrive_expect_tx(mb_local + 8 * i, 4096u);
        }
        asm volatile("fence.mbarrier_init.release.cluster;" ::: "memory");
    }
    __syncthreads();
    asm volatile("barrier.cluster.arrive.aligned;" ::: "memory");
    asm volatile("barrier.cluster.wait.aligned;" ::: "memory");

    // remote addresses
    const uint32_t hbase = smem_u32(&hsp[0][0][0][0]);
    const uint32_t sbase = smem_u32(&stg[0][0][0]);
    uint32_t rh[CL], rm[CL];
#pragma unroll
    for (int r = 0; r < CL; r++) {
        rh[r] = mapa_rank(hbase, (uint32_t)r);
        rm[r] = mapa_rank(mb_local, (uint32_t)r);
    }
    const uint32_t my_off = rank * 512u;      // my slice inside a (grp,slot) block
    const int sidx = (oj >> 1) * 4 + obl * 2 + (oj & 1);

    const size_t obaseA = (size_t)(b0 + obl) * SS * HH + gj;
    const size_t obaseB = (size_t)(b0 + 2 + obl) * SS * HH + gj;
    float xpA = __ldcs(out + obaseA);
    float xpB = __ldcs(out + obaseB);
    float hlA = 0.f, hlB = 0.f;
    uint32_t phA0 = 0, phA1 = 0, phB0 = 0, phB1 = 0;

#define GSTEP(T, S, G, PH, XP, HL, OBASE)                                       \
  {                                                                             \
    if ((T) > 0) {                                                              \
      mbar_wait_cluster(mb_local + ((G) * 2 + (S)) * 8, PH);                    \
      PH ^= 1u;                                                                 \
      if (tid == 0) mbar_arrive_expect_tx(mb_local + ((G) * 2 + (S)) * 8, 4096u);\
    }                                                                           \
    const ull* hb = &hsp[G][S][w * 32][0];                                      \
    ull a00 = 0, a01 = 0, a10 = 0, a11 = 0;                                     \
    _Pragma("unroll")                                                           \
    for (int p = 0; p < 32; p++) {                                              \
      ulonglong2 hx = *(const ulonglong2*)(hb + p * 2);                         \
      ull w0 = Wp0[p], w1 = Wp1[p];                                             \
      ffma2(a00, hx.x, w0); ffma2(a01, hx.y, w0);                               \
      ffma2(a10, hx.x, w1); ffma2(a11, hx.y, w1);                               \
    }                                                                           \
    { float2 f; float2 ra, rb;                                                  \
      f = unpack2(a00); ra.x = f.x + f.y; f = unpack2(a01); ra.y = f.x + f.y;   \
      f = unpack2(a10); rb.x = f.x + f.y; f = unpack2(a11); rb.y = f.x + f.y;   \
      *(float2*)&red[G][0][w][l][0] = ra;                                       \
      *(float2*)&red[G][1][w][l][0] = rb; }                                     \
    __syncthreads();                                                            \
    const float* rf = &red[G][oj & 1][0][oj >> 1][obl];                         \
    float sum = rf[0] + rf[64] + rf[128] + rf[192]                              \
              + rf[256] + rf[320] + rf[384] + rf[448];                          \
    float pre = XP + sum + bh;                                                  \
    float e = __expf(pre + pre);                                                \
    float hv = 1.f - __fdividef(2.f, e + 1.f);                                  \
    stg[G][S][sidx] = hv;                                                       \
    __syncthreads();                                                            \
    if (((T) + 1 < SS) && tid < CL) {                                           \
      asm volatile("fence.proxy.async.shared::cta;" ::: "memory");              \
      bulk_copy_cluster(                                                        \
          rh[tid] + (uint32_t)((G) * 8192 + ((S) ^ 1) * 4096) + my_off,         \
          sbase + (uint32_t)(((G) * 2 + (S)) * 512), 512u,                      \
          rm[tid] + (uint32_t)(((G) * 2 + ((S) ^ 1)) * 8));                     \
    }                                                                           \
    __stcs(out + OBASE + (size_t)(T) * HH, hv);                                 \
    HL = hv;                                                                    \
    if ((T) + 1 < SS) XP = __ldcs(out + OBASE + (size_t)((T) + 1) * HH);        \
  }

    for (int t = 0; t < SS; t += 2) {
        GSTEP(t,     0, 0, phA0, xpA, hlA, obaseA);
        GSTEP(t,     0, 1, phB0, xpB, hlB, obaseB);
        GSTEP(t + 1, 1, 0, phA1, xpA, hlA, obaseA);
        GSTEP(t + 1, 1, 1, phB1, xpB, hlB, obaseB);
    }
#undef GSTEP

    if (write_hfinal) {
        out[(size_t)BB * SS * HH + (size_t)(b0 + obl) * HH + gj] = hlA;
        out[(size_t)BB * SS * HH + (size_t)(b0 + 2 + obl) * HH + gj] = hlB;
    }
}

// ---------------- launch ----------------
extern "C" void kernel_launch(void* const* d_in, const int* in_sizes, int n_in,
                              void* d_out, int out_size) {
    const float* inputs = (const float*)d_in[0];   // [64, 2048, 512]
    const float* h0     = (const float*)d_in[1];   // [64, 512]
    const float* W_ih   = (const float*)d_in[2];   // [512, 512]
    const float* W_hh   = (const float*)d_in[3];   // [512, 512]
    const float* b_ih   = (const float*)d_in[4];   // [512]
    const float* b_hh   = (const float*)d_in[5];   // [512]
    float* out = (float*)d_out;

    // Phase 1: x_proj into the outs region of d_out (scan overwrites in place)
    dim3 g1((BB * SS) / 128, HH / 128, 1);
    xproj_kernel<<<g1, 256>>>(inputs, W_ih, b_ih, out);

    // Phase 2: 16 clusters of 8 CTAs, two interleaved recurrences per cluster
    long long need = (long long)BB * SS * HH + (long long)BB * HH;
    int wf = ((long long)out_size >= need) ? 1 : 0;
    rnn_scan_kernel<<<NCTA, 256>>>(h0, W_hh, b_hh, out, wf);
}